// round 6
// baseline (speedup 1.0000x reference)
#include <cuda_runtime.h>
#include <cuda_bf16.h>
#include <cstdint>

// ContrastiveLoss: N=8192, D=256, 64 classes, T=0.5.
// loss = sum_i [ P_i*(2 + log denom_i) - possum_i ] / n_pos
//   denom_i  = sum_{j!=i} exp(sim_ij - 2)   (shift-invariant; sim<=2, unit-norm)
//   possum_i = sum_{j: lab_j==lab_i, j!=i} sim_ij
// sim = E@E^T via bf16 mma.sync, upper-triangular tiles only; off-diagonal
// tiles feed row- AND column-block stats in a single exp pass.
// R5: 64x64 warp tiles (4 warps/CTA) -> 3x less ldsm traffic; fused epilogue.

#define N_ROWS 8192
#define DIM    256
#define NCLS   64
#define BM     128
#define BN     128
#define KCHUNK 64
#define NCHUNK (DIM / KCHUNK)          // 4
#define SSTRIDE 72                     // bf16 elems per smem row (64 + 8 pad)
#define NB     (N_ROWS / BM)           // 64 tile-blocks per side
#define NTILES (NB * (NB + 1) / 2)     // 2080 upper-tri tiles

__device__ float g_denom[N_ROWS];
__device__ float g_pos[N_ROWS];
__device__ __nv_bfloat16 g_Ebf[N_ROWS * DIM];

__device__ __forceinline__ uint32_t smem_u32(const void* p) {
    uint32_t a;
    asm("{ .reg .u64 t; cvta.to.shared.u64 t, %1; cvt.u32.u64 %0, t; }" : "=r"(a) : "l"(p));
    return a;
}
__device__ __forceinline__ void ldsm_x4(uint32_t& r0, uint32_t& r1, uint32_t& r2, uint32_t& r3,
                                        uint32_t addr) {
    asm volatile("ldmatrix.sync.aligned.m8n8.x4.shared.b16 {%0,%1,%2,%3}, [%4];"
                 : "=r"(r0), "=r"(r1), "=r"(r2), "=r"(r3) : "r"(addr));
}
__device__ __forceinline__ void mma16816(float* d, const uint32_t* a, uint32_t b0, uint32_t b1) {
    asm volatile(
        "mma.sync.aligned.m16n8k16.row.col.f32.bf16.bf16.f32 "
        "{%0,%1,%2,%3}, {%4,%5,%6,%7}, {%8,%9}, {%0,%1,%2,%3};"
        : "+f"(d[0]), "+f"(d[1]), "+f"(d[2]), "+f"(d[3])
        : "r"(a[0]), "r"(a[1]), "r"(a[2]), "r"(a[3]), "r"(b0), "r"(b1));
}
#define CP_ASYNC16(sm, gp) asm volatile("cp.async.cg.shared.global [%0], [%1], 16;" :: "r"(sm), "l"(gp) : "memory")
#define CP_COMMIT()        asm volatile("cp.async.commit_group;" ::: "memory")
#define CP_WAIT(n)         asm volatile("cp.async.wait_group %0;" :: "n"(n) : "memory")

// ---- label width detection: int64 labels (<64) have zero high words ----
__device__ __forceinline__ int detect_is64(const int* L) {
    int s = 0;
#pragma unroll
    for (int k = 0; k < 64; k++) s |= L[2 * k + 1];
    return (s == 0) ? 1 : 0;
}
__device__ __forceinline__ int get_label(const int* L, int i, int is64) {
    return is64 ? L[2 * i] : L[i];
}

// ---- prep: zero accumulators + convert E to bf16 ----
__global__ void prep_kernel(const float* __restrict__ E) {
    int i = blockIdx.x * blockDim.x + threadIdx.x;   // one float4 per thread
    if (i < N_ROWS) { g_denom[i] = 0.f; g_pos[i] = 0.f; }
    float4 v = ((const float4*)E)[i];
    __nv_bfloat162 p0 = __floats2bfloat162_rn(v.x, v.y);
    __nv_bfloat162 p1 = __floats2bfloat162_rn(v.z, v.w);
    uint2 o;
    o.x = *(uint32_t*)&p0;
    o.y = *(uint32_t*)&p1;
    ((uint2*)g_Ebf)[i] = o;
}

// ---- fused HMMA GEMM + single-pass dual epilogue, upper-tri tiles ----
// 128 threads = 4 warps in 2(m) x 2(n); warp tile 64x64; thread acc 128 fp32.
__global__ __launch_bounds__(128, 2)
void sim_kernel(const int* __restrict__ Lraw) {
    extern __shared__ __nv_bfloat16 smem[];   // [2 stages][A 128*72 | B 128*72]
    __shared__ int   labI[BM], labJ[BN];
    __shared__ float redD[BM], redP[BM];      // row-block partials
    __shared__ float redDc[BN], redPc[BN];    // col-block partials
    __shared__ int   s_is64;

    const int tid  = threadIdx.x;
    const int wid  = tid >> 5, lane = tid & 31;
    const int wm   = wid >> 1, wn = wid & 1;          // 2x2 warp grid

    // ---- linear tile id -> upper-triangular (bi, bj) ----
    const int t = blockIdx.x;
    int bi = (int)((2.0f * NB + 1.0f -
                    sqrtf((2.0f * NB + 1.0f) * (2.0f * NB + 1.0f) - 8.0f * (float)t)) * 0.5f);
    while (bi > 0 && bi * NB - bi * (bi - 1) / 2 > t) bi--;
    while ((bi + 1) * NB - (bi + 1) * bi / 2 <= t) bi++;
    const int bj = bi + (t - (bi * NB - bi * (bi - 1) / 2));
    const int row0 = bi * BM, col0 = bj * BN;
    const bool offdiag = (bi != bj);

    const uint32_t sbase = smem_u32(smem);
    const uint32_t stageBytes = 2u * 2u * BM * SSTRIDE;     // A+B one stage (bytes)

    if (tid == 0) s_is64 = detect_is64(Lraw);
    if (tid < BM) { redD[tid] = 0.f; redP[tid] = 0.f; redDc[tid] = 0.f; redPc[tid] = 0.f; }

    // ---- async tile loader: chunk c (k = c*KCHUNK), stage s ----
    auto load_chunk = [&](int c, int s) {
        const __nv_bfloat16* gA = g_Ebf + (size_t)row0 * DIM + c * KCHUNK;
        const __nv_bfloat16* gB = g_Ebf + (size_t)col0 * DIM + c * KCHUNK;
        uint32_t stA = sbase + s * stageBytes;
        uint32_t stB = stA + 2u * BM * SSTRIDE;
#pragma unroll
        for (int u = 0; u < 8; u++) {
            int idx = tid + u * 128;               // 0..1023 16B units
            int r = idx >> 3, c16 = idx & 7;
            uint32_t so = (uint32_t)(r * SSTRIDE + c16 * 8) * 2u;
            CP_ASYNC16(stA + so, gA + (size_t)r * DIM + c16 * 8);
            CP_ASYNC16(stB + so, gB + (size_t)r * DIM + c16 * 8);
        }
    };

    float acc[4][8][4];                        // mf x nf x elem = 128 regs
#pragma unroll
    for (int mf = 0; mf < 4; mf++)
#pragma unroll
        for (int nf = 0; nf < 8; nf++)
#pragma unroll
            for (int e = 0; e < 4; e++) acc[mf][nf][e] = 0.f;

    load_chunk(0, 0);
    CP_COMMIT();
    __syncthreads();                           // publishes s_is64 / red* zeros

    if (tid < BM) {
        labI[tid] = get_label(Lraw, row0 + tid, s_is64);
        labJ[tid] = get_label(Lraw, col0 + tid, s_is64);
    }

    // fragment address components (within a stage)
    const uint32_t aRow = (uint32_t)(wm * 64 + (lane & 15));
    const uint32_t aKof = (uint32_t)((lane >> 4) * 8);
    const uint32_t bRow = (uint32_t)(wn * 64 + (lane & 7) + ((lane >> 4) << 3));
    const uint32_t bKof = (uint32_t)(((lane >> 3) & 1) * 8);

    for (int c = 0; c < NCHUNK; c++) {
        if (c + 1 < NCHUNK) {
            load_chunk(c + 1, (c + 1) & 1);
            CP_COMMIT();
            CP_WAIT(1);
        } else {
            CP_WAIT(0);
        }
        __syncthreads();

        uint32_t stA = sbase + (c & 1) * stageBytes;
        uint32_t stB = stA + 2u * BM * SSTRIDE;
#pragma unroll
        for (int k16 = 0; k16 < KCHUNK / 16; k16++) {
            const uint32_t k0 = k16 * 16;
            uint32_t a[4][4], b[4][4];
#pragma unroll
            for (int mf = 0; mf < 4; mf++)
                ldsm_x4(a[mf][0], a[mf][1], a[mf][2], a[mf][3],
                        stA + ((aRow + mf * 16) * SSTRIDE + k0 + aKof) * 2u);
#pragma unroll
            for (int nb = 0; nb < 4; nb++)
                ldsm_x4(b[nb][0], b[nb][1], b[nb][2], b[nb][3],
                        stB + ((bRow + nb * 16) * SSTRIDE + k0 + bKof) * 2u);
#pragma unroll
            for (int mf = 0; mf < 4; mf++)
#pragma unroll
                for (int nf = 0; nf < 8; nf++)
                    mma16816(acc[mf][nf], a[mf], b[nf >> 1][(nf & 1) * 2],
                             b[nf >> 1][(nf & 1) * 2 + 1]);
        }
        __syncthreads();
    }

    // ---- single-pass epilogue: one exp per element feeds row AND col sums ----
    const int rbase = wm * 64 + (lane >> 2);   // + mf*16 + 8h
    int   li[8];
#pragma unroll
    for (int mf = 0; mf < 4; mf++)
#pragma unroll
        for (int h = 0; h < 2; h++) li[mf * 2 + h] = labI[rbase + mf * 16 + 8 * h];

    float dR[8], pR[8];
#pragma unroll
    for (int x = 0; x < 8; x++) { dR[x] = 0.f; pR[x] = 0.f; }

#pragma unroll
    for (int nf = 0; nf < 8; nf++) {
#pragma unroll
        for (int e = 0; e < 2; e++) {
            const int cloc = wn * 64 + nf * 8 + 2 * (lane & 3) + e;
            const int lj = labJ[cloc];
            float dc = 0.f, pc = 0.f;
#pragma unroll
            for (int mf = 0; mf < 4; mf++) {
#pragma unroll
                for (int h = 0; h < 2; h++) {
                    const int idx = mf * 2 + h;
                    const int rloc = rbase + mf * 16 + 8 * h;
                    const float s = 2.0f * acc[mf][nf][h * 2 + e];   // /TEMPERATURE
                    const float ex = __expf(s - 2.0f);
                    const bool self = (!offdiag) && (rloc == cloc);
                    const bool eq = (li[idx] == lj);
                    if (!self) {
                        dR[idx] += ex;
                        if (eq) pR[idx] += s;
                        dc += ex;
                        if (eq) pc += s;
                    }
                }
            }
            if (offdiag) {
                dc += __shfl_xor_sync(0xFFFFFFFF, dc, 4);
                dc += __shfl_xor_sync(0xFFFFFFFF, dc, 8);
                dc += __shfl_xor_sync(0xFFFFFFFF, dc, 16);
                pc += __shfl_xor_sync(0xFFFFFFFF, pc, 4);
                pc += __shfl_xor_sync(0xFFFFFFFF, pc, 8);
                pc += __shfl_xor_sync(0xFFFFFFFF, pc, 16);
                if ((lane >> 2) == 0) {
                    atomicAdd(&redDc[cloc], dc);
                    atomicAdd(&redPc[cloc], pc);
                }
            }
        }
    }
#pragma unroll
    for (int x = 0; x < 8; x++) {
        float d = dR[x], p = pR[x];
        d += __shfl_xor_sync(0xFFFFFFFF, d, 1);
        d += __shfl_xor_sync(0xFFFFFFFF, d, 2);
        p += __shfl_xor_sync(0xFFFFFFFF, p, 1);
        p += __shfl_xor_sync(0xFFFFFFFF, p, 2);
        if ((lane & 3) == 0) {
            const int rloc = rbase + (x >> 1) * 16 + 8 * (x & 1);
            atomicAdd(&redD[rloc], d);
            atomicAdd(&redP[rloc], p);
        }
    }

    __syncthreads();
    if (tid < BM) {
        atomicAdd(&g_denom[row0 + tid], redD[tid]);
        atomicAdd(&g_pos[row0 + tid],   redP[tid]);
        if (offdiag) {
            atomicAdd(&g_denom[col0 + tid], redDc[tid]);
            atomicAdd(&g_pos[col0 + tid],   redPc[tid]);
        }
    }
}

// ---- finalize: label histogram, per-row combine, scalar loss ----
__global__ void finalize_kernel(const int* __restrict__ Lraw, float* __restrict__ out) {
    __shared__ int cnt[NCLS];
    __shared__ double red[256];
    __shared__ int s_is64;
    const int tid = threadIdx.x;

    if (tid == 0) s_is64 = detect_is64(Lraw);
    if (tid < NCLS) cnt[tid] = 0;
    __syncthreads();
    const int is64 = s_is64;

    for (int i = tid; i < N_ROWS; i += 256)
        atomicAdd(&cnt[get_label(Lraw, i, is64)], 1);
    __syncthreads();

    double acc = 0.0;
    for (int i = tid; i < N_ROWS; i += 256) {
        int P = cnt[get_label(Lraw, i, is64)] - 1;
        acc += (double)P * (2.0 + (double)logf(g_denom[i])) - (double)g_pos[i];
    }
    red[tid] = acc;
    __syncthreads();
    for (int s = 128; s > 0; s >>= 1) {
        if (tid < s) red[tid] += red[tid + s];
        __syncthreads();
    }
    if (tid == 0) {
        long long npos = 0;
        for (int c = 0; c < NCLS; c++)
            npos += (long long)cnt[c] * (long long)(cnt[c] - 1);
        out[0] = (float)(red[0] / (double)npos);
    }
}

extern "C" void kernel_launch(void* const* d_in, const int* in_sizes, int n_in,
                              void* d_out, int out_size) {
    const float* E    = (const float*)d_in[0];
    const int*   Lraw = (const int*)d_in[1];   // width auto-detected on device
    float* out = (float*)d_out;

    const int DYN_SMEM = 2 * 2 * 2 * BM * SSTRIDE;   // 2 stages * (A+B) bytes = 73728
    cudaFuncSetAttribute(sim_kernel, cudaFuncAttributeMaxDynamicSharedMemorySize, DYN_SMEM);

    prep_kernel<<<(N_ROWS * DIM / 4) / 256, 256>>>(E);
    sim_kernel<<<NTILES, 128, DYN_SMEM>>>(Lraw);
    finalize_kernel<<<1, 256>>>(Lraw, out);
}

// round 7
// speedup vs baseline: 1.1014x; 1.1014x over previous
#include <cuda_runtime.h>
#include <cuda_bf16.h>
#include <cstdint>

// ContrastiveLoss: N=8192, D=256, 64 classes, T=0.5.
// loss = sum_i [ P_i*(2 + log denom_i) - possum_i ] / n_pos
//   denom_i  = sum_{j!=i} exp(sim_ij - 2)   (shift-invariant; sim<=2, unit-norm)
//   possum_i = sum_{j: lab_j==lab_i, j!=i} sim_ij
// R6: sim = E@E^T in FP8 e4m3 via mma.sync m16n8k32 (halves L2+smem traffic
// and HMMA count vs bf16). Upper-triangular tiles; single-pass row+col epilogue.

#define N_ROWS 8192
#define DIM    256                     // fp8 elements per row (= 256 bytes)
#define DIMH   128                     // in b16 (packed fp8-pair) units
#define NCLS   64
#define BM     128
#define BN     128
#define SSTRIDE 136                    // b16 units per smem row (128 + 8 pad)
#define NB     (N_ROWS / BM)           // 64
#define NTILES (NB * (NB + 1) / 2)     // 2080 upper-tri tiles

__device__ float g_denom[N_ROWS];
__device__ float g_pos[N_ROWS];
__device__ uint8_t g_E8[N_ROWS * DIM];

__device__ __forceinline__ uint32_t smem_u32(const void* p) {
    uint32_t a;
    asm("{ .reg .u64 t; cvta.to.shared.u64 t, %1; cvt.u32.u64 %0, t; }" : "=r"(a) : "l"(p));
    return a;
}
__device__ __forceinline__ void ldsm_x4(uint32_t& r0, uint32_t& r1, uint32_t& r2, uint32_t& r3,
                                        uint32_t addr) {
    asm volatile("ldmatrix.sync.aligned.m8n8.x4.shared.b16 {%0,%1,%2,%3}, [%4];"
                 : "=r"(r0), "=r"(r1), "=r"(r2), "=r"(r3) : "r"(addr));
}
// fp8 e4m3 MMA: same fragment register shape as bf16 m16n8k16, k doubled.
__device__ __forceinline__ void mma_fp8(float* d, const uint32_t* a, uint32_t b0, uint32_t b1) {
    asm volatile(
        "mma.sync.aligned.m16n8k32.row.col.f32.e4m3.e4m3.f32 "
        "{%0,%1,%2,%3}, {%4,%5,%6,%7}, {%8,%9}, {%0,%1,%2,%3};"
        : "+f"(d[0]), "+f"(d[1]), "+f"(d[2]), "+f"(d[3])
        : "r"(a[0]), "r"(a[1]), "r"(a[2]), "r"(a[3]), "r"(b0), "r"(b1));
}
#define CP_ASYNC16(sm, gp) asm volatile("cp.async.cg.shared.global [%0], [%1], 16;" :: "r"(sm), "l"(gp) : "memory")
#define CP_COMMIT()        asm volatile("cp.async.commit_group;" ::: "memory")
#define CP_WAIT0()         asm volatile("cp.async.wait_group 0;" ::: "memory")

// ---- label width detection: int64 labels (<64) have zero high words ----
__device__ __forceinline__ int detect_is64(const int* L) {
    int s = 0;
#pragma unroll
    for (int k = 0; k < 64; k++) s |= L[2 * k + 1];
    return (s == 0) ? 1 : 0;
}
__device__ __forceinline__ int get_label(const int* L, int i, int is64) {
    return is64 ? L[2 * i] : L[i];
}

// ---- prep: zero accumulators + convert E to fp8 e4m3 ----
__global__ void prep_kernel(const float* __restrict__ E) {
    int i = blockIdx.x * blockDim.x + threadIdx.x;   // one float4 -> 4 fp8
    if (i < N_ROWS) { g_denom[i] = 0.f; g_pos[i] = 0.f; }
    float4 v = ((const float4*)E)[i];
    uint16_t h0, h1;
    asm("cvt.rn.satfinite.e4m3x2.f32 %0, %1, %2;" : "=h"(h0) : "f"(v.y), "f"(v.x));
    asm("cvt.rn.satfinite.e4m3x2.f32 %0, %1, %2;" : "=h"(h1) : "f"(v.w), "f"(v.z));
    ((uint32_t*)g_E8)[i] = (uint32_t)h0 | ((uint32_t)h1 << 16);
}

// ---- fused FP8 HMMA GEMM + single-pass dual epilogue, upper-tri tiles ----
// 256 threads = 8 warps in 2(m) x 4(n); warp tile 64x32; full K resident.
__global__ __launch_bounds__(256, 2)
void sim_kernel(const int* __restrict__ Lraw) {
    extern __shared__ __align__(16) char smem[];   // A[128][136]b16 | B[128][136]b16
    __shared__ int   labI[BM], labJ[BN];
    __shared__ float redD[BM], redP[BM];
    __shared__ float redDc[BN], redPc[BN];
    __shared__ int   s_is64;

    const int tid  = threadIdx.x;
    const int wid  = tid >> 5, lane = tid & 31;
    const int wm   = wid >> 2, wn = wid & 3;          // 2x4 warp grid

    // ---- linear tile id -> upper-triangular (bi, bj) ----
    const int t = blockIdx.x;
    int bi = (int)((2.0f * NB + 1.0f -
                    sqrtf((2.0f * NB + 1.0f) * (2.0f * NB + 1.0f) - 8.0f * (float)t)) * 0.5f);
    while (bi > 0 && bi * NB - bi * (bi - 1) / 2 > t) bi--;
    while ((bi + 1) * NB - (bi + 1) * bi / 2 <= t) bi++;
    const int bj = bi + (t - (bi * NB - bi * (bi - 1) / 2));
    const int row0 = bi * BM, col0 = bj * BN;
    const bool offdiag = (bi != bj);

    const uint32_t sbase = smem_u32(smem);
    const uint32_t stB_off = 2u * BM * SSTRIDE;       // bytes to B tile

    if (tid == 0) s_is64 = detect_is64(Lraw);
    if (tid < BM) { redD[tid] = 0.f; redP[tid] = 0.f; redDc[tid] = 0.f; redPc[tid] = 0.f; }

    // ---- one-shot async load of full A and B tiles (128 x 256B each) ----
    {
        const uint8_t* gA = g_E8 + (size_t)row0 * DIM;
        const uint8_t* gB = g_E8 + (size_t)col0 * DIM;
#pragma unroll
        for (int u = 0; u < 8; u++) {
            int idx = tid + u * 256;                   // 0..2047 16B units
            int r = idx >> 4, c16 = idx & 15;
            uint32_t so = (uint32_t)(r * (SSTRIDE * 2) + c16 * 16);
            const size_t go = (size_t)r * DIM + c16 * 16;
            CP_ASYNC16(sbase + so, gA + go);
            CP_ASYNC16(sbase + stB_off + so, gB + go);
        }
        CP_COMMIT();
    }

    float acc[4][4][4];
#pragma unroll
    for (int mf = 0; mf < 4; mf++)
#pragma unroll
        for (int nf = 0; nf < 4; nf++)
#pragma unroll
            for (int e = 0; e < 4; e++) acc[mf][nf][e] = 0.f;

    __syncthreads();                                   // publish s_is64 / red zeros
    if (tid < BM) {
        labI[tid] = get_label(Lraw, row0 + tid, s_is64);
        labJ[tid] = get_label(Lraw, col0 + tid, s_is64);
    }

    // fragment address components (b16-unit coords, x2 for bytes)
    const uint32_t aRow = (uint32_t)(wm * 64 + (lane & 15));
    const uint32_t aKof = (uint32_t)((lane >> 4) * 8);
    const uint32_t bRow = (uint32_t)(wn * 32 + (lane & 7) + ((lane >> 4) << 3));
    const uint32_t bKof = (uint32_t)(((lane >> 3) & 1) * 8);

    CP_WAIT0();
    __syncthreads();

    // ---- mainloop: 8 k-steps of 16 b16 (= k32 fp8), no further syncs ----
#pragma unroll
    for (int ks = 0; ks < DIMH / 16; ks++) {
        const uint32_t k0 = ks * 16;
        uint32_t a[4][4], b[2][4];
#pragma unroll
        for (int mf = 0; mf < 4; mf++)
            ldsm_x4(a[mf][0], a[mf][1], a[mf][2], a[mf][3],
                    sbase + ((aRow + mf * 16) * SSTRIDE + k0 + aKof) * 2u);
#pragma unroll
        for (int nb = 0; nb < 2; nb++)
            ldsm_x4(b[nb][0], b[nb][1], b[nb][2], b[nb][3],
                    sbase + stB_off + ((bRow + nb * 16) * SSTRIDE + k0 + bKof) * 2u);
#pragma unroll
        for (int mf = 0; mf < 4; mf++)
#pragma unroll
            for (int nf = 0; nf < 4; nf++)
                mma_fp8(acc[mf][nf], a[mf], b[nf >> 1][(nf & 1) * 2],
                        b[nf >> 1][(nf & 1) * 2 + 1]);
    }

    // ---- single-pass epilogue: one exp per element feeds row AND col sums ----
    const int rbase = wm * 64 + (lane >> 2);
    int li[8];
#pragma unroll
    for (int mf = 0; mf < 4; mf++)
#pragma unroll
        for (int h = 0; h < 2; h++) li[mf * 2 + h] = labI[rbase + mf * 16 + 8 * h];

    float dR[8], pR[8];
#pragma unroll
    for (int x = 0; x < 8; x++) { dR[x] = 0.f; pR[x] = 0.f; }

#pragma unroll
    for (int nf = 0; nf < 4; nf++) {
#pragma unroll
        for (int e = 0; e < 2; e++) {
            const int cloc = wn * 32 + nf * 8 + 2 * (lane & 3) + e;
            const int lj = labJ[cloc];
            float dc = 0.f, pc = 0.f;
#pragma unroll
            for (int mf = 0; mf < 4; mf++) {
#pragma unroll
                for (int h = 0; h < 2; h++) {
                    const int idx = mf * 2 + h;
                    const int rloc = rbase + mf * 16 + 8 * h;
                    const float s = 2.0f * acc[mf][nf][h * 2 + e];   // /TEMPERATURE
                    const float ex = __expf(s - 2.0f);
                    const bool self = (!offdiag) && (rloc == cloc);
                    const bool eq = (li[idx] == lj);
                    if (!self) {
                        dR[idx] += ex;
                        if (eq) pR[idx] += s;
                        dc += ex;
                        if (eq) pc += s;
                    }
                }
            }
            if (offdiag) {
                dc += __shfl_xor_sync(0xFFFFFFFF, dc, 4);
                dc += __shfl_xor_sync(0xFFFFFFFF, dc, 8);
                dc += __shfl_xor_sync(0xFFFFFFFF, dc, 16);
                pc += __shfl_xor_sync(0xFFFFFFFF, pc, 4);
                pc += __shfl_xor_sync(0xFFFFFFFF, pc, 8);
                pc += __shfl_xor_sync(0xFFFFFFFF, pc, 16);
                if ((lane >> 2) == 0) {
                    atomicAdd(&redDc[cloc], dc);
                    atomicAdd(&redPc[cloc], pc);
                }
            }
        }
    }
#pragma unroll
    for (int x = 0; x < 8; x++) {
        float d = dR[x], p = pR[x];
        d += __shfl_xor_sync(0xFFFFFFFF, d, 1);
        d += __shfl_xor_sync(0xFFFFFFFF, d, 2);
        p += __shfl_xor_sync(0xFFFFFFFF, p, 1);
        p += __shfl_xor_sync(0xFFFFFFFF, p, 2);
        if ((lane & 3) == 0) {
            const int rloc = rbase + (x >> 1) * 16 + 8 * (x & 1);
            atomicAdd(&redD[rloc], d);
            atomicAdd(&redP[rloc], p);
        }
    }

    __syncthreads();
    if (tid < BM) {
        atomicAdd(&g_denom[row0 + tid], redD[tid]);
        atomicAdd(&g_pos[row0 + tid],   redP[tid]);
        if (offdiag) {
            atomicAdd(&g_denom[col0 + tid], redDc[tid]);
            atomicAdd(&g_pos[col0 + tid],   redPc[tid]);
        }
    }
}

// ---- finalize: label histogram, per-row combine, scalar loss ----
__global__ void finalize_kernel(const int* __restrict__ Lraw, float* __restrict__ out) {
    __shared__ int cnt[NCLS];
    __shared__ double red[256];
    __shared__ int s_is64;
    const int tid = threadIdx.x;

    if (tid == 0) s_is64 = detect_is64(Lraw);
    if (tid < NCLS) cnt[tid] = 0;
    __syncthreads();
    const int is64 = s_is64;

    for (int i = tid; i < N_ROWS; i += 256)
        atomicAdd(&cnt[get_label(Lraw, i, is64)], 1);
    __syncthreads();

    double acc = 0.0;
    for (int i = tid; i < N_ROWS; i += 256) {
        int P = cnt[get_label(Lraw, i, is64)] - 1;
        acc += (double)P * (2.0 + (double)logf(g_denom[i])) - (double)g_pos[i];
    }
    red[tid] = acc;
    __syncthreads();
    for (int s = 128; s > 0; s >>= 1) {
        if (tid < s) red[tid] += red[tid + s];
        __syncthreads();
    }
    if (tid == 0) {
        long long npos = 0;
        for (int c = 0; c < NCLS; c++)
            npos += (long long)cnt[c] * (long long)(cnt[c] - 1);
        out[0] = (float)(red[0] / (double)npos);
    }
}

extern "C" void kernel_launch(void* const* d_in, const int* in_sizes, int n_in,
                              void* d_out, int out_size) {
    const float* E    = (const float*)d_in[0];
    const int*   Lraw = (const int*)d_in[1];   // width auto-detected on device
    float* out = (float*)d_out;

    const int DYN_SMEM = 2 * 2 * BM * SSTRIDE;   // A+B tiles, full K: 69632 B
    cudaFuncSetAttribute(sim_kernel, cudaFuncAttributeMaxDynamicSharedMemorySize, DYN_SMEM);

    prep_kernel<<<(N_ROWS * DIM / 4) / 256, 256>>>(E);
    sim_kernel<<<NTILES, 256, DYN_SMEM>>>(Lraw);
    finalize_kernel<<<1, 256>>>(Lraw, out);
}